// round 4
// baseline (speedup 1.0000x reference)
#include <cuda_runtime.h>
#include <cstdint>

#define BB 4096
#define MAXN 12
#define HID 301
#define NT 10
#define PP 9
#define VSTAT 310   // HID + PP
#define KP 320      // padded K / hidden stride
#define KP4 80      // KP/4

#define SSTR 36     // smem row stride in floats (conflict-free + 16B aligned)
#define JT 16       // j-cols per block

// ---------------- scratch (device globals; zero-initialized) ----------------
__device__ float d_g[(size_t)BB * 11 * KP];     // gated vectors per node 0..10
__device__ float d_hcur[(size_t)BB * KP];       // current hidden (fp32, for head)
__device__ float d_hin[(size_t)BB * KP];        // aggregated message (fp32)
__device__ float d_hA1[(size_t)BB * KP];        // tf32 split of hcur (gate GEMM A)
__device__ float d_hA2[(size_t)BB * KP];
__device__ float d_iA1[(size_t)BB * KP];        // tf32 split of hin (GRU GEMM A)
__device__ float d_iA2[(size_t)BB * KP];
__device__ float d_Whh1[960 * KP];              // tf32 splits of padded W_hh
__device__ float d_Whh2[960 * KP];
__device__ float d_Wgm1[640 * KP];              // tf32 splits of padded [Wg;Wm]
__device__ float d_Wgm2[640 * KP];

__device__ __forceinline__ float sigm(float x) { return 1.f / (1.f + __expf(-x)); }

__device__ __forceinline__ uint32_t f2tf32(float x) {
    uint32_t r; asm("cvt.rna.tf32.f32 %0, %1;" : "=r"(r) : "f"(x)); return r;
}
__device__ __forceinline__ void tf32split(float x, float& hi, float& lo) {
    uint32_t h = f2tf32(x);
    hi = __uint_as_float(h);
    lo = __uint_as_float(f2tf32(x - hi));
}
__device__ __forceinline__ void mma_tf32(float c[4], const uint32_t a[4],
                                         uint32_t b0, uint32_t b1) {
    asm volatile(
        "mma.sync.aligned.m16n8k8.row.col.f32.tf32.tf32.f32 "
        "{%0,%1,%2,%3}, {%4,%5,%6,%7}, {%8,%9}, {%0,%1,%2,%3};"
        : "+f"(c[0]), "+f"(c[1]), "+f"(c[2]), "+f"(c[3])
        : "r"(a[0]), "r"(a[1]), "r"(a[2]), "r"(a[3]), "r"(b0), "r"(b1));
}
__device__ __forceinline__ void cpa16(uint32_t s, const void* g) {
    asm volatile("cp.async.ca.shared.global [%0], [%1], 16;" :: "r"(s), "l"(g));
}
#define CP_COMMIT() asm volatile("cp.async.commit_group;")
template<int N> __device__ __forceinline__ void cp_wait() {
    asm volatile("cp.async.wait_group %0;" :: "n"(N));
}

// ---------------- weight repack + tf32 split (pads stay zero) ---------------
__global__ void k_pad(const float* __restrict__ Whh, const float* __restrict__ Wg,
                      const float* __restrict__ Wm)
{
    int idx = blockIdx.x * blockDim.x + threadIdx.x;
    const int total = HID * HID;
    if (idx < 3 * total) {
        int s = idx / total, r = idx - s * total, j = r / HID, k = r - j * HID;
        float hi, lo;
        tf32split(Whh[(s * HID + j) * HID + k], hi, lo);
        d_Whh1[(s * KP + j) * KP + k] = hi;
        d_Whh2[(s * KP + j) * KP + k] = lo;
    } else if (idx < 5 * total) {
        int m = (idx - 3 * total) / total, r = (idx - 3 * total) % total;
        int j = r / HID, k = r - j * HID;
        const float* W = m ? Wm : Wg;
        float hi, lo;
        tf32split(W[j * VSTAT + k], hi, lo);
        d_Wgm1[(m * KP + j) * KP + k] = hi;
        d_Wgm2[(m * KP + j) * KP + k] = lo;
    }
}

// ---------------- node 0: h0 = gru(x0, 0) -----------------------------------
__global__ void k_h0(const int* __restrict__ types, const int* __restrict__ paths,
                     const float* __restrict__ W_ih, const float* __restrict__ b_ih,
                     const float* __restrict__ b_hh)
{
    int idx = blockIdx.x * blockDim.x + threadIdx.x;
    if (idx >= BB * HID) return;
    int b = idx / HID, j = idx - b * HID;
    int t = types[b * MAXN], p = paths[b * MAXN];
    float ir  = W_ih[j * 19 + t]            + W_ih[j * 19 + NT + p]            + b_ih[j];
    float iz  = W_ih[(j + HID) * 19 + t]    + W_ih[(j + HID) * 19 + NT + p]    + b_ih[j + HID];
    float inn = W_ih[(j + 2*HID) * 19 + t]  + W_ih[(j + 2*HID) * 19 + NT + p]  + b_ih[j + 2*HID];
    float r = sigm(ir + b_hh[j]);
    float z = sigm(iz + b_hh[j + HID]);
    float n = tanhf(inn + r * b_hh[j + 2*HID]);
    float h = (1.f - z) * n;
    size_t o = (size_t)b * KP + j;
    d_hcur[o] = h;
    float hi, lo; tf32split(h, hi, lo);
    d_hA1[o] = hi; d_hA2[o] = lo;
}

// ---------------- h_in = sum adj*g ; emit fp32 + splits ---------------------
__global__ void k_hin(const int* __restrict__ adj, int v)
{
    int t = threadIdx.x;          // 0..319
    int lb = t / KP4, c4 = t - lb * KP4;
    int b = blockIdx.x * 4 + lb;
    const float4* g4 = (const float4*)d_g;
    const int* arow = adj + b * (MAXN * MAXN) + v * MAXN;
    float4 acc = make_float4(0.f, 0.f, 0.f, 0.f);
    for (int u = 0; u < v; ++u) {
        if (arow[u]) {
            float4 gv = g4[((size_t)b * 11 + u) * KP4 + c4];
            acc.x += gv.x; acc.y += gv.y; acc.z += gv.z; acc.w += gv.w;
        }
    }
    size_t o = (size_t)b * KP4 + c4;
    ((float4*)d_hin)[o] = acc;
    float4 h1, h2;
    tf32split(acc.x, h1.x, h2.x); tf32split(acc.y, h1.y, h2.y);
    tf32split(acc.z, h1.z, h2.z); tf32split(acc.w, h1.w, h2.w);
    ((float4*)d_iA1)[o] = h1;
    ((float4*)d_iA2)[o] = h2;
}

// ============================================================================
// Fused GRU GEMM+epilogue.
// Block: 128 batch x 16 j-cols x 3 gates. Warps: 4(M) x 2(N). 3xTF32.
// A = hin splits, B = Whh splits. Epilogue: full GRU cell, emits hcur + splits.
// ============================================================================
#define GRU_AS (128 * SSTR)
#define GRU_BS (48 * SSTR)
#define GRU_STG (2 * GRU_AS + 2 * GRU_BS)
#define GRU_SMEM (2 * GRU_STG * 4)

__global__ void __launch_bounds__(256, 2) k_ggru(int v,
    const int* __restrict__ types, const int* __restrict__ paths,
    const float* __restrict__ W_ih,
    const float* __restrict__ b_ih, const float* __restrict__ b_hh)
{
    extern __shared__ float sm[];
    int tid = threadIdx.x, lane = tid & 31, wid = tid >> 5;
    int g = lane >> 2, tig = lane & 3;
    int wm = wid >> 1, wn = wid & 1;
    int b0 = blockIdx.x * 128, j0 = blockIdx.y * JT;

    float c[2][3][4];
#pragma unroll
    for (int mf = 0; mf < 2; ++mf)
#pragma unroll
        for (int s = 0; s < 3; ++s)
#pragma unroll
            for (int i = 0; i < 4; ++i) c[mf][s][i] = 0.f;

    uint32_t sbase = (uint32_t)__cvta_generic_to_shared(sm);

    auto loadStage = [&](int stage, int k0) {
        uint32_t sa = sbase + stage * GRU_STG * 4;
        // A: 2048 float4 (A1 then A2)
#pragma unroll
        for (int q = 0; q < 8; ++q) {
            int idx = tid + 256 * q;
            int half = idx >= 1024;
            int i2 = idx - half * 1024;
            int r = i2 >> 3, cc = i2 & 7;
            const float* src = (half ? d_iA2 : d_iA1) + (size_t)(b0 + r) * KP + k0 + cc * 4;
            cpa16(sa + (half * GRU_AS + r * SSTR + cc * 4) * 4, src);
        }
        // B: 768 float4 (B1 then B2), 48 rows = 3 gates x 16 j
#pragma unroll
        for (int q = 0; q < 3; ++q) {
            int idx = tid + 256 * q;
            int half = idx >= 384;
            int i2 = idx - half * 384;
            int r = i2 >> 3, cc = i2 & 7;
            int s = r >> 4, jt = r & 15;
            const float* src = (half ? d_Whh2 : d_Whh1) +
                               (size_t)(s * KP + j0 + jt) * KP + k0 + cc * 4;
            cpa16(sa + (2 * GRU_AS + half * GRU_BS + r * SSTR + cc * 4) * 4, src);
        }
    };

    loadStage(0, 0);
    CP_COMMIT();

    for (int kb = 0; kb < 10; ++kb) {
        if (kb < 9) { loadStage((kb + 1) & 1, (kb + 1) * 32); CP_COMMIT(); cp_wait<1>(); }
        else        { cp_wait<0>(); }
        __syncthreads();
        float* base = sm + (kb & 1) * GRU_STG;
        float* sA1 = base;
        float* sA2 = base + GRU_AS;
        float* sB1 = base + 2 * GRU_AS;
        float* sB2 = sB1 + GRU_BS;

#pragma unroll
        for (int k8 = 0; k8 < 4; ++k8) {
            int kc = k8 * 8 + tig;
            float bh[3][2], bl[3][2];
#pragma unroll
            for (int s = 0; s < 3; ++s) {
                int br = s * 16 + wn * 8 + g;
                bh[s][0] = sB1[br * SSTR + kc]; bh[s][1] = sB1[br * SSTR + kc + 4];
                bl[s][0] = sB2[br * SSTR + kc]; bl[s][1] = sB2[br * SSTR + kc + 4];
            }
            uint32_t ah[2][4], al[2][4];
#pragma unroll
            for (int mf = 0; mf < 2; ++mf) {
                int mr = wm * 32 + mf * 16 + g;
                ah[mf][0] = __float_as_uint(sA1[mr * SSTR + kc]);
                ah[mf][1] = __float_as_uint(sA1[(mr + 8) * SSTR + kc]);
                ah[mf][2] = __float_as_uint(sA1[mr * SSTR + kc + 4]);
                ah[mf][3] = __float_as_uint(sA1[(mr + 8) * SSTR + kc + 4]);
                al[mf][0] = __float_as_uint(sA2[mr * SSTR + kc]);
                al[mf][1] = __float_as_uint(sA2[(mr + 8) * SSTR + kc]);
                al[mf][2] = __float_as_uint(sA2[mr * SSTR + kc + 4]);
                al[mf][3] = __float_as_uint(sA2[(mr + 8) * SSTR + kc + 4]);
            }
#pragma unroll
            for (int mf = 0; mf < 2; ++mf)
#pragma unroll
                for (int s = 0; s < 3; ++s) {
                    uint32_t bh0 = __float_as_uint(bh[s][0]), bh1 = __float_as_uint(bh[s][1]);
                    mma_tf32(c[mf][s], ah[mf], bh0, bh1);
                    mma_tf32(c[mf][s], ah[mf], __float_as_uint(bl[s][0]),
                                               __float_as_uint(bl[s][1]));
                    mma_tf32(c[mf][s], al[mf], bh0, bh1);
                }
        }
        __syncthreads();
    }

    // ---- fused GRU epilogue (register-resident r,z,n) ----
    int jc0 = j0 + wn * 8 + 2 * tig;
#pragma unroll
    for (int mf = 0; mf < 2; ++mf) {
#pragma unroll
        for (int hf = 0; hf < 2; ++hf) {
            int row = b0 + wm * 32 + mf * 16 + g + hf * 8;
            int ci = hf * 2;
            int t = types[row * MAXN + v], p = paths[row * MAXN + v];
#pragma unroll
            for (int cl = 0; cl < 2; ++cl) {
                int j = jc0 + cl;
                float h = 0.f;
                if (j < HID) {
                    float hin = d_hin[(size_t)row * KP + j];
                    const float* w0 = W_ih + (size_t)j * 19;
                    const float* w1 = W_ih + (size_t)(j + HID) * 19;
                    const float* w2 = W_ih + (size_t)(j + 2 * HID) * 19;
                    float rr = sigm(c[mf][0][ci + cl] + w0[t] + w0[NT + p] +
                                    b_ih[j] + b_hh[j]);
                    float zz = sigm(c[mf][1][ci + cl] + w1[t] + w1[NT + p] +
                                    b_ih[j + HID] + b_hh[j + HID]);
                    float nn = tanhf(w2[t] + w2[NT + p] + b_ih[j + 2 * HID] +
                                     rr * (c[mf][2][ci + cl] + b_hh[j + 2 * HID]));
                    h = (1.f - zz) * nn + zz * hin;
                }
                size_t o = (size_t)row * KP + j;
                d_hcur[o] = h;
                float hh, hl; tf32split(h, hh, hl);
                d_hA1[o] = hh; d_hA2[o] = hl;
            }
        }
    }
}

// ============================================================================
// Fused gate GEMM+epilogue. Block: 128 batch x 16 j x 2 mats (Wg, Wm).
// A = hcur splits, B = Wgm splits. Epilogue: sigmoid(g)*m -> d_g[:,v,:].
// ============================================================================
#define GT_AS (128 * SSTR)
#define GT_BS (32 * SSTR)
#define GT_STG (2 * GT_AS + 2 * GT_BS)
#define GT_SMEM (2 * GT_STG * 4)

__global__ void __launch_bounds__(256, 2) k_ggate(int v,
    const int* __restrict__ paths,
    const float* __restrict__ Wg, const float* __restrict__ bg,
    const float* __restrict__ Wm)
{
    extern __shared__ float sm[];
    int tid = threadIdx.x, lane = tid & 31, wid = tid >> 5;
    int g = lane >> 2, tig = lane & 3;
    int wm = wid >> 1, wn = wid & 1;
    int b0 = blockIdx.x * 128, j0 = blockIdx.y * JT;

    float c[2][2][4];
#pragma unroll
    for (int mf = 0; mf < 2; ++mf)
#pragma unroll
        for (int s = 0; s < 2; ++s)
#pragma unroll
            for (int i = 0; i < 4; ++i) c[mf][s][i] = 0.f;

    uint32_t sbase = (uint32_t)__cvta_generic_to_shared(sm);

    auto loadStage = [&](int stage, int k0) {
        uint32_t sa = sbase + stage * GT_STG * 4;
#pragma unroll
        for (int q = 0; q < 8; ++q) {
            int idx = tid + 256 * q;
            int half = idx >= 1024;
            int i2 = idx - half * 1024;
            int r = i2 >> 3, cc = i2 & 7;
            const float* src = (half ? d_hA2 : d_hA1) + (size_t)(b0 + r) * KP + k0 + cc * 4;
            cpa16(sa + (half * GT_AS + r * SSTR + cc * 4) * 4, src);
        }
#pragma unroll
        for (int q = 0; q < 2; ++q) {
            int idx = tid + 256 * q;
            int half = idx >= 256;
            int i2 = idx - half * 256;
            int r = i2 >> 3, cc = i2 & 7;
            int s = r >> 4, jt = r & 15;
            const float* src = (half ? d_Wgm2 : d_Wgm1) +
                               (size_t)(s * KP + j0 + jt) * KP + k0 + cc * 4;
            cpa16(sa + (2 * GT_AS + half * GT_BS + r * SSTR + cc * 4) * 4, src);
        }
    };

    loadStage(0, 0);
    CP_COMMIT();

    for (int kb = 0; kb < 10; ++kb) {
        if (kb < 9) { loadStage((kb + 1) & 1, (kb + 1) * 32); CP_COMMIT(); cp_wait<1>(); }
        else        { cp_wait<0>(); }
        __syncthreads();
        float* base = sm + (kb & 1) * GT_STG;
        float* sA1 = base;
        float* sA2 = base + GT_AS;
        float* sB1 = base + 2 * GT_AS;
        float* sB2 = sB1 + GT_BS;

#pragma unroll
        for (int k8 = 0; k8 < 4; ++k8) {
            int kc = k8 * 8 + tig;
            float bh[2][2], bl[2][2];
#pragma unroll
            for (int s = 0; s < 2; ++s) {
                int br = s * 16 + wn * 8 + g;
                bh[s][0] = sB1[br * SSTR + kc]; bh[s][1] = sB1[br * SSTR + kc + 4];
                bl[s][0] = sB2[br * SSTR + kc]; bl[s][1] = sB2[br * SSTR + kc + 4];
            }
            uint32_t ah[2][4], al[2][4];
#pragma unroll
            for (int mf = 0; mf < 2; ++mf) {
                int mr = wm * 32 + mf * 16 + g;
                ah[mf][0] = __float_as_uint(sA1[mr * SSTR + kc]);
                ah[mf][1] = __float_as_uint(sA1[(mr + 8) * SSTR + kc]);
                ah[mf][2] = __float_as_uint(sA1[mr * SSTR + kc + 4]);
                ah[mf][3] = __float_as_uint(sA1[(mr + 8) * SSTR + kc + 4]);
                al[mf][0] = __float_as_uint(sA2[mr * SSTR + kc]);
                al[mf][1] = __float_as_uint(sA2[(mr + 8) * SSTR + kc]);
                al[mf][2] = __float_as_uint(sA2[mr * SSTR + kc + 4]);
                al[mf][3] = __float_as_uint(sA2[(mr + 8) * SSTR + kc + 4]);
            }
#pragma unroll
            for (int mf = 0; mf < 2; ++mf)
#pragma unroll
                for (int s = 0; s < 2; ++s) {
                    uint32_t bh0 = __float_as_uint(bh[s][0]), bh1 = __float_as_uint(bh[s][1]);
                    mma_tf32(c[mf][s], ah[mf], bh0, bh1);
                    mma_tf32(c[mf][s], ah[mf], __float_as_uint(bl[s][0]),
                                               __float_as_uint(bl[s][1]));
                    mma_tf32(c[mf][s], al[mf], bh0, bh1);
                }
        }
        __syncthreads();
    }

    // ---- fused gate epilogue ----
    int jc0 = j0 + wn * 8 + 2 * tig;
#pragma unroll
    for (int mf = 0; mf < 2; ++mf) {
#pragma unroll
        for (int hf = 0; hf < 2; ++hf) {
            int row = b0 + wm * 32 + mf * 16 + g + hf * 8;
            int ci = hf * 2;
            int p = paths[row * MAXN + v];
#pragma unroll
            for (int cl = 0; cl < 2; ++cl) {
                int j = jc0 + cl;
                float val = 0.f;
                if (j < HID) {
                    float gv = sigm(c[mf][0][ci + cl] + Wg[(size_t)j * VSTAT + HID + p] + bg[j]);
                    float mv = c[mf][1][ci + cl] + Wm[(size_t)j * VSTAT + HID + p];
                    val = gv * mv;
                }
                d_g[((size_t)row * 11 + v) * KP + j] = val;
            }
        }
    }
}

// ---------------- head ------------------------------------------------------
__global__ void __launch_bounds__(128) k_head(
    const int* __restrict__ paths, const float* __restrict__ feats,
    const float* __restrict__ W_df1, const float* __restrict__ b_df1,
    const float* __restrict__ W_df2, const float* __restrict__ b_df2,
    const float* __restrict__ W_fc1, const float* __restrict__ b_fc1,
    const float* __restrict__ W_fc2, const float* __restrict__ b_fc2,
    float* __restrict__ out)
{
    int b = blockIdx.x;
    int t = threadIdx.x;
    __shared__ float hg[HID + 8];
    __shared__ float df[3 * PP];
    __shared__ float hid16[16];

    for (int j = t; j < HID; j += 128) hg[j] = d_hcur[(size_t)b * KP + j];
    if (t < 3 * PP) df[t] = 0.f;
    __syncthreads();
    if (t == 0) {
        for (int v = 0; v < MAXN; ++v) {
            int base = paths[b * MAXN + v] * 3;
            df[base]     = feats[(b * MAXN + v) * 3 + 0];
            df[base + 1] = feats[(b * MAXN + v) * 3 + 1];
            df[base + 2] = feats[(b * MAXN + v) * 3 + 2];
        }
    }
    __syncthreads();
    if (t < 16) {
        float a = b_df1[t];
        for (int k = 0; k < 3 * PP; ++k) a = fmaf(df[k], W_df1[t * (3 * PP) + k], a);
        hid16[t] = fmaxf(a, 0.f);
    }
    __syncthreads();
    if (t < 8) {
        float a = b_df2[t];
        for (int k = 0; k < 16; ++k) a = fmaf(hid16[k], W_df2[t * 16 + k], a);
        hg[HID + t] = a;
    }
    __syncthreads();
    if (t < 112) {
        const float* W;
        float a;
        int i;
        if (t < 56) { i = t;      W = W_fc1; a = b_fc1[i]; }
        else        { i = t - 56; W = W_fc2; a = b_fc2[i]; }
        const float* wrow = W + i * (HID + 8);
        for (int k = 0; k < HID + 8; ++k) a = fmaf(hg[k], wrow[k], a);
        out[b * 112 + t] = a;
    }
}

// ---------------- launcher --------------------------------------------------
extern "C" void kernel_launch(void* const* d_in, const int* in_sizes, int n_in,
                              void* d_out, int out_size)
{
    const int*   types = (const int*)d_in[0];
    const int*   paths = (const int*)d_in[1];
    const int*   adj   = (const int*)d_in[2];
    const float* feats = (const float*)d_in[3];
    const float* W_ih  = (const float*)d_in[4];
    const float* W_hh  = (const float*)d_in[5];
    const float* b_ih  = (const float*)d_in[6];
    const float* b_hh  = (const float*)d_in[7];
    const float* Wg    = (const float*)d_in[8];
    const float* bg    = (const float*)d_in[9];
    const float* Wm    = (const float*)d_in[10];
    const float* W_df1 = (const float*)d_in[11];
    const float* b_df1 = (const float*)d_in[12];
    const float* W_df2 = (const float*)d_in[13];
    const float* b_df2 = (const float*)d_in[14];
    const float* W_fc1 = (const float*)d_in[15];
    const float* b_fc1 = (const float*)d_in[16];
    const float* W_fc2 = (const float*)d_in[17];
    const float* b_fc2 = (const float*)d_in[18];
    float* out = (float*)d_out;

    cudaFuncSetAttribute(k_ggru,  cudaFuncAttributeMaxDynamicSharedMemorySize, GRU_SMEM);
    cudaFuncSetAttribute(k_ggate, cudaFuncAttributeMaxDynamicSharedMemorySize, GT_SMEM);

    dim3 gGemm(BB / 128, KP / JT);   // 32 x 20 = 640 blocks

    k_pad<<<(5 * HID * HID + 255) / 256, 256>>>(W_hh, Wg, Wm);
    k_h0<<<(BB * HID + 255) / 256, 256>>>(types, paths, W_ih, b_ih, b_hh);

    k_ggate<<<gGemm, 256, GT_SMEM>>>(0, paths, Wg, bg, Wm);
    for (int v = 1; v < MAXN; ++v) {
        k_hin<<<BB / 4, 4 * KP4>>>(adj, v);
        k_ggru<<<gGemm, 256, GRU_SMEM>>>(v, types, paths, W_ih, b_ih, b_hh);
        if (v < MAXN - 1)
            k_ggate<<<gGemm, 256, GT_SMEM>>>(v, paths, Wg, bg, Wm);
    }
    k_head<<<BB, 128>>>(paths, feats, W_df1, b_df1, W_df2, b_df2,
                        W_fc1, b_fc1, W_fc2, b_fc2, out);
}

// round 5
// speedup vs baseline: 1.1714x; 1.1714x over previous
#include <cuda_runtime.h>
#include <cuda_bf16.h>
#include <cstdint>

#define BB 4096
#define MAXN 12
#define HID 301
#define NT 10
#define PP 9
#define VSTAT 310   // HID + PP
#define KP 320      // padded hidden size
#define KP4 80      // KP/4
#define KS 960      // split-K: [hi(320) | lo(320) | hi(320)] activations
                    //          [hi(320) | hi(320) | lo(320)] weights
#define SST 40      // smem row stride in bf16 units (80B; conflict-free)
#define JT 32       // j-cols per block

// ---------------- scratch (device globals; zero-initialized) ----------------
__device__ float d_g[(size_t)BB * 11 * KP];      // gated vectors (fp32)
__device__ float d_hcur[(size_t)BB * KP];        // current hidden (fp32)
__device__ float d_hin[(size_t)BB * KP];         // aggregated message (fp32)
__device__ __nv_bfloat16 d_hAS[(size_t)BB * KS]; // split of hcur (gate GEMM A)
__device__ __nv_bfloat16 d_iAS[(size_t)BB * KS]; // split of hin  (GRU GEMM A)
__device__ __nv_bfloat16 d_WhhS[960 * KS];       // split W_hh (rows s*320+j)
__device__ __nv_bfloat16 d_WgmS[640 * KS];       // split [Wg;Wm]

__device__ __forceinline__ float sigm(float x) { return 1.f / (1.f + __expf(-x)); }

__device__ __forceinline__ void bsplit(float x, __nv_bfloat16& hi, __nv_bfloat16& lo) {
    hi = __float2bfloat16_rn(x);
    lo = __float2bfloat16_rn(x - __bfloat162float(hi));
}

__device__ __forceinline__ void mma_bf16(float c[4], const uint32_t a[4],
                                         uint32_t b0, uint32_t b1) {
    asm volatile(
        "mma.sync.aligned.m16n8k16.row.col.f32.bf16.bf16.f32 "
        "{%0,%1,%2,%3}, {%4,%5,%6,%7}, {%8,%9}, {%0,%1,%2,%3};"
        : "+f"(c[0]), "+f"(c[1]), "+f"(c[2]), "+f"(c[3])
        : "r"(a[0]), "r"(a[1]), "r"(a[2]), "r"(a[3]), "r"(b0), "r"(b1));
}
__device__ __forceinline__ void cpa16(uint32_t s, const void* g) {
    asm volatile("cp.async.ca.shared.global [%0], [%1], 16;" :: "r"(s), "l"(g));
}
#define CP_COMMIT() asm volatile("cp.async.commit_group;")
template<int N> __device__ __forceinline__ void cp_wait() {
    asm volatile("cp.async.wait_group %0;" :: "n"(N));
}

// ---------------- weight repack + bf16 split (pads stay zero) ---------------
__global__ void k_pad(const float* __restrict__ Whh, const float* __restrict__ Wg,
                      const float* __restrict__ Wm)
{
    int idx = blockIdx.x * blockDim.x + threadIdx.x;
    const int total = HID * HID;
    if (idx < 3 * total) {
        int s = idx / total, r = idx - s * total, j = r / HID, k = r - j * HID;
        __nv_bfloat16 hi, lo;
        bsplit(Whh[(s * HID + j) * HID + k], hi, lo);
        size_t row = (size_t)(s * KP + j) * KS;
        d_WhhS[row + k] = hi;
        d_WhhS[row + KP + k] = hi;
        d_WhhS[row + 2 * KP + k] = lo;
    } else if (idx < 5 * total) {
        int m = (idx - 3 * total) / total, r = (idx - 3 * total) % total;
        int j = r / HID, k = r - j * HID;
        const float* W = m ? Wm : Wg;
        __nv_bfloat16 hi, lo;
        bsplit(W[j * VSTAT + k], hi, lo);
        size_t row = (size_t)(m * KP + j) * KS;
        d_WgmS[row + k] = hi;
        d_WgmS[row + KP + k] = hi;
        d_WgmS[row + 2 * KP + k] = lo;
    }
}

// ---------------- node 0: h0 = gru(x0, 0) -----------------------------------
__global__ void k_h0(const int* __restrict__ types, const int* __restrict__ paths,
                     const float* __restrict__ W_ih, const float* __restrict__ b_ih,
                     const float* __restrict__ b_hh)
{
    int idx = blockIdx.x * blockDim.x + threadIdx.x;
    if (idx >= BB * HID) return;
    int b = idx / HID, j = idx - b * HID;
    int t = types[b * MAXN], p = paths[b * MAXN];
    float ir  = W_ih[j * 19 + t]            + W_ih[j * 19 + NT + p]            + b_ih[j];
    float iz  = W_ih[(j + HID) * 19 + t]    + W_ih[(j + HID) * 19 + NT + p]    + b_ih[j + HID];
    float inn = W_ih[(j + 2*HID) * 19 + t]  + W_ih[(j + 2*HID) * 19 + NT + p]  + b_ih[j + 2*HID];
    float r = sigm(ir + b_hh[j]);
    float z = sigm(iz + b_hh[j + HID]);
    float n = tanhf(inn + r * b_hh[j + 2*HID]);
    float h = (1.f - z) * n;
    d_hcur[(size_t)b * KP + j] = h;
    __nv_bfloat16 hi, lo; bsplit(h, hi, lo);
    size_t o = (size_t)b * KS + j;
    d_hAS[o] = hi; d_hAS[o + KP] = lo; d_hAS[o + 2 * KP] = hi;
}

// ---------------- h_in = sum adj*g ; emit fp32 + bf16 splits ----------------
__global__ void k_hin(const int* __restrict__ adj, int v)
{
    int t = threadIdx.x;          // 0..319
    int lb = t / KP4, c4 = t - lb * KP4;
    int b = blockIdx.x * 4 + lb;
    const float4* g4 = (const float4*)d_g;
    const int* arow = adj + b * (MAXN * MAXN) + v * MAXN;
    float4 acc = make_float4(0.f, 0.f, 0.f, 0.f);
    for (int u = 0; u < v; ++u) {
        if (arow[u]) {
            float4 gv = g4[((size_t)b * 11 + u) * KP4 + c4];
            acc.x += gv.x; acc.y += gv.y; acc.z += gv.z; acc.w += gv.w;
        }
    }
    ((float4*)d_hin)[(size_t)b * KP4 + c4] = acc;
    __nv_bfloat16 hx, lx, hy, ly, hz, lz, hw, lw;
    bsplit(acc.x, hx, lx); bsplit(acc.y, hy, ly);
    bsplit(acc.z, hz, lz); bsplit(acc.w, hw, lw);
    size_t o = (size_t)b * KS + 4 * c4;
    __nv_bfloat162* p0 = (__nv_bfloat162*)(d_iAS + o);
    p0[0] = __nv_bfloat162{hx, hy}; p0[1] = __nv_bfloat162{hz, hw};
    __nv_bfloat162* p1 = (__nv_bfloat162*)(d_iAS + o + KP);
    p1[0] = __nv_bfloat162{lx, ly}; p1[1] = __nv_bfloat162{lz, lw};
    __nv_bfloat162* p2 = (__nv_bfloat162*)(d_iAS + o + 2 * KP);
    p2[0] = __nv_bfloat162{hx, hy}; p2[1] = __nv_bfloat162{hz, hw};
}

// ============================================================================
// Fused GRU GEMM+epilogue. Block: 128 batch x 32 j x 3 gates, K=960 bf16.
// Warps 4(M) x 2(N). Epilogue: full GRU cell -> hcur fp32 + bf16 splits.
// ============================================================================
#define STAGE_A (128 * SST)                 // 5120 bf16
#define GRU_STAGE (STAGE_A + 96 * SST)      // + 3840 = 8960 bf16 (17920 B)
#define GRU_SMEM (2 * GRU_STAGE * 2)
#define GT_STAGE (STAGE_A + 64 * SST)       // 7680 bf16 (15360 B)
#define GT_SMEM (2 * GT_STAGE * 2)

__global__ void __launch_bounds__(256, 2) k_ggru(int v,
    const int* __restrict__ types, const int* __restrict__ paths,
    const float* __restrict__ W_ih,
    const float* __restrict__ b_ih, const float* __restrict__ b_hh)
{
    extern __shared__ __nv_bfloat16 sm[];
    int tid = threadIdx.x, lane = tid & 31, wid = tid >> 5;
    int g = lane >> 2, tig = lane & 3;
    int wm = wid >> 1, wn = wid & 1;
    int b0 = blockIdx.x * 128, j0 = blockIdx.y * JT;

    float c[2][3][2][4];
#pragma unroll
    for (int mf = 0; mf < 2; ++mf)
#pragma unroll
        for (int s = 0; s < 3; ++s)
#pragma unroll
            for (int nf = 0; nf < 2; ++nf)
#pragma unroll
                for (int i = 0; i < 4; ++i) c[mf][s][nf][i] = 0.f;

    uint32_t sbase = (uint32_t)__cvta_generic_to_shared(sm);

    auto loadStage = [&](int st, int k0) {
        uint32_t sa = sbase + st * GRU_STAGE * 2;
        // A: 128 rows x 64B = 512 x 16B
#pragma unroll
        for (int q = 0; q < 2; ++q) {
            int idx = tid + 256 * q;
            int r = idx >> 2, cc = idx & 3;
            cpa16(sa + (r * SST + cc * 8) * 2,
                  d_iAS + (size_t)(b0 + r) * KS + k0 + cc * 8);
        }
        // B: 96 rows x 64B = 384 x 16B
#pragma unroll
        for (int q = 0; q < 2; ++q) {
            int idx = tid + 256 * q;
            if (idx < 384) {
                int r = idx >> 2, cc = idx & 3;
                int s = r >> 5, jt = r & 31;
                cpa16(sa + (STAGE_A + r * SST + cc * 8) * 2,
                      d_WhhS + (size_t)(s * KP + j0 + jt) * KS + k0 + cc * 8);
            }
        }
    };

    loadStage(0, 0);
    CP_COMMIT();

    for (int kb = 0; kb < 30; ++kb) {
        if (kb < 29) { loadStage((kb + 1) & 1, (kb + 1) * 32); CP_COMMIT(); cp_wait<1>(); }
        else         { cp_wait<0>(); }
        __syncthreads();
        const __nv_bfloat16* sA = sm + (kb & 1) * GRU_STAGE;
        const __nv_bfloat16* sB = sA + STAGE_A;
#pragma unroll
        for (int k16 = 0; k16 < 2; ++k16) {
            int ko = k16 * 16 + 2 * tig;
            uint32_t a[2][4];
#pragma unroll
            for (int mf = 0; mf < 2; ++mf) {
                int mr = wm * 32 + mf * 16 + g;
                a[mf][0] = *(const uint32_t*)&sA[mr * SST + ko];
                a[mf][1] = *(const uint32_t*)&sA[(mr + 8) * SST + ko];
                a[mf][2] = *(const uint32_t*)&sA[mr * SST + ko + 8];
                a[mf][3] = *(const uint32_t*)&sA[(mr + 8) * SST + ko + 8];
            }
#pragma unroll
            for (int s = 0; s < 3; ++s)
#pragma unroll
                for (int nf = 0; nf < 2; ++nf) {
                    int br = s * 32 + wn * 16 + nf * 8 + g;
                    uint32_t bb0 = *(const uint32_t*)&sB[br * SST + ko];
                    uint32_t bb1 = *(const uint32_t*)&sB[br * SST + ko + 8];
#pragma unroll
                    for (int mf = 0; mf < 2; ++mf)
                        mma_bf16(c[mf][s][nf], a[mf], bb0, bb1);
                }
        }
        __syncthreads();
    }

    // ---- fused GRU epilogue ----
#pragma unroll
    for (int mf = 0; mf < 2; ++mf) {
#pragma unroll
        for (int hf = 0; hf < 2; ++hf) {
            int row = b0 + wm * 32 + mf * 16 + g + hf * 8;
            int t = types[row * MAXN + v], p = paths[row * MAXN + v];
#pragma unroll
            for (int nf = 0; nf < 2; ++nf) {
                int jb = j0 + wn * 16 + nf * 8 + 2 * tig;
                float h2[2];
#pragma unroll
                for (int cl = 0; cl < 2; ++cl) {
                    int j = jb + cl;
                    int ci = hf * 2 + cl;
                    float h = 0.f;
                    if (j < HID) {
                        float hin = d_hin[(size_t)row * KP + j];
                        const float* w0 = W_ih + (size_t)j * 19;
                        const float* w1 = W_ih + (size_t)(j + HID) * 19;
                        const float* w2 = W_ih + (size_t)(j + 2 * HID) * 19;
                        float rr = sigm(c[mf][0][nf][ci] + w0[t] + w0[NT + p] +
                                        b_ih[j] + b_hh[j]);
                        float zz = sigm(c[mf][1][nf][ci] + w1[t] + w1[NT + p] +
                                        b_ih[j + HID] + b_hh[j + HID]);
                        float nn = tanhf(w2[t] + w2[NT + p] + b_ih[j + 2 * HID] +
                                         rr * (c[mf][2][nf][ci] + b_hh[j + 2 * HID]));
                        h = (1.f - zz) * nn + zz * hin;
                    }
                    h2[cl] = h;
                }
                *(float2*)&d_hcur[(size_t)row * KP + jb] = make_float2(h2[0], h2[1]);
                __nv_bfloat16 h0h, h0l, h1h, h1l;
                bsplit(h2[0], h0h, h0l); bsplit(h2[1], h1h, h1l);
                size_t o = (size_t)row * KS + jb;
                *(__nv_bfloat162*)(d_hAS + o)          = __nv_bfloat162{h0h, h1h};
                *(__nv_bfloat162*)(d_hAS + o + KP)     = __nv_bfloat162{h0l, h1l};
                *(__nv_bfloat162*)(d_hAS + o + 2 * KP) = __nv_bfloat162{h0h, h1h};
            }
        }
    }
}

// ============================================================================
// Fused gate GEMM+epilogue. Block: 128 batch x 32 j x 2 mats, K=960 bf16.
// ============================================================================
__global__ void __launch_bounds__(256, 2) k_ggate(int v,
    const int* __restrict__ paths,
    const float* __restrict__ Wg, const float* __restrict__ bg,
    const float* __restrict__ Wm)
{
    extern __shared__ __nv_bfloat16 sm[];
    int tid = threadIdx.x, lane = tid & 31, wid = tid >> 5;
    int g = lane >> 2, tig = lane & 3;
    int wm = wid >> 1, wn = wid & 1;
    int b0 = blockIdx.x * 128, j0 = blockIdx.y * JT;

    float c[2][2][2][4];
#pragma unroll
    for (int mf = 0; mf < 2; ++mf)
#pragma unroll
        for (int s = 0; s < 2; ++s)
#pragma unroll
            for (int nf = 0; nf < 2; ++nf)
#pragma unroll
                for (int i = 0; i < 4; ++i) c[mf][s][nf][i] = 0.f;

    uint32_t sbase = (uint32_t)__cvta_generic_to_shared(sm);

    auto loadStage = [&](int st, int k0) {
        uint32_t sa = sbase + st * GT_STAGE * 2;
#pragma unroll
        for (int q = 0; q < 2; ++q) {
            int idx = tid + 256 * q;
            int r = idx >> 2, cc = idx & 3;
            cpa16(sa + (r * SST + cc * 8) * 2,
                  d_hAS + (size_t)(b0 + r) * KS + k0 + cc * 8);
        }
        {
            int idx = tid;              // 64 rows x 4 = 256 ops
            int r = idx >> 2, cc = idx & 3;
            int s = r >> 5, jt = r & 31;
            cpa16(sa + (STAGE_A + r * SST + cc * 8) * 2,
                  d_WgmS + (size_t)(s * KP + j0 + jt) * KS + k0 + cc * 8);
        }
    };

    loadStage(0, 0);
    CP_COMMIT();

    for (int kb = 0; kb < 30; ++kb) {
        if (kb < 29) { loadStage((kb + 1) & 1, (kb + 1) * 32); CP_COMMIT(); cp_wait<1>(); }
        else         { cp_wait<0>(); }
        __syncthreads();
        const __nv_bfloat16* sA = sm + (kb & 1) * GT_STAGE;
        const __nv_bfloat16* sB = sA + STAGE_A;
#pragma unroll
        for (int k16 = 0; k16 < 2; ++k16) {
            int ko = k16 * 16 + 2 * tig;
            uint32_t a[2][4];
#pragma unroll
            for (int mf = 0; mf < 2; ++mf) {
                int mr = wm * 32 + mf * 16 + g;
                a[mf][0] = *(const uint32_t*)&sA[mr * SST + ko];
                a[mf][1] = *(const uint32_t*)&sA[(mr + 8) * SST + ko];
                a[mf][2] = *(const uint32_t*)&sA[mr * SST + ko + 8];
                a[mf][3] = *(const uint32_t*)&sA[(mr + 8) * SST + ko + 8];
            }
#pragma unroll
            for (int s = 0; s < 2; ++s)
#pragma unroll
                for (int nf = 0; nf < 2; ++nf) {
                    int br = s * 32 + wn * 16 + nf * 8 + g;
                    uint32_t bb0 = *(const uint32_t*)&sB[br * SST + ko];
                    uint32_t bb1 = *(const uint32_t*)&sB[br * SST + ko + 8];
#pragma unroll
                    for (int mf = 0; mf < 2; ++mf)
                        mma_bf16(c[mf][s][nf], a[mf], bb0, bb1);
                }
        }
        __syncthreads();
    }

    // ---- fused gate epilogue ----
#pragma unroll
    for (int mf = 0; mf < 2; ++mf) {
#pragma unroll
        for (int hf = 0; hf < 2; ++hf) {
            int row = b0 + wm * 32 + mf * 16 + g + hf * 8;
            int p = paths[row * MAXN + v];
#pragma unroll
            for (int nf = 0; nf < 2; ++nf) {
                int jb = j0 + wn * 16 + nf * 8 + 2 * tig;
                float v2[2];
#pragma unroll
                for (int cl = 0; cl < 2; ++cl) {
                    int j = jb + cl;
                    int ci = hf * 2 + cl;
                    float val = 0.f;
                    if (j < HID) {
                        float gv = sigm(c[mf][0][nf][ci] +
                                        Wg[(size_t)j * VSTAT + HID + p] + bg[j]);
                        float mv = c[mf][1][nf][ci] + Wm[(size_t)j * VSTAT + HID + p];
                        val = gv * mv;
                    }
                    v2[cl] = val;
                }
                *(float2*)&d_g[((size_t)row * 11 + v) * KP + jb] = make_float2(v2[0], v2[1]);
            }
        }
    }
}

// ---------------- head ------------------------------------------------------
__global__ void __launch_bounds__(128) k_head(
    const int* __restrict__ paths, const float* __restrict__ feats,
    const float* __restrict__ W_df1, const float* __restrict__ b_df1,
    const float* __restrict__ W_df2, const float* __restrict__ b_df2,
    const float* __restrict__ W_fc1, const float* __restrict__ b_fc1,
    const float* __restrict__ W_fc2, const float* __restrict__ b_fc2,
    float* __restrict__ out)
{
    int b = blockIdx.x;
    int t = threadIdx.x;
    __shared__ float hg[HID + 8];
    __shared__ float df[3 * PP];
    __shared__ float hid16[16];

    for (int j = t; j < HID; j += 128) hg[j] = d_hcur[(size_t)b * KP + j];
    if (t < 3 * PP) df[t] = 0.f;
    __syncthreads();
    if (t == 0) {
        for (int v = 0; v < MAXN; ++v) {
            int base = paths[b * MAXN + v] * 3;
            df[base]     = feats[(b * MAXN + v) * 3 + 0];
            df[base + 1] = feats[(b * MAXN + v) * 3 + 1];
            df[base + 2] = feats[(b * MAXN + v) * 3 + 2];
        }
    }
    __syncthreads();
    if (t < 16) {
        float a = b_df1[t];
        for (int k = 0; k < 3 * PP; ++k) a = fmaf(df[k], W_df1[t * (3 * PP) + k], a);
        hid16[t] = fmaxf(a, 0.f);
    }
    __syncthreads();
    if (t < 8) {
        float a = b_df2[t];
        for (int k = 0; k < 16; ++k) a = fmaf(hid16[k], W_df2[t * 16 + k], a);
        hg[HID + t] = a;
    }
    __syncthreads();
    if (t < 112) {
        const float* W;
        float a;
        int i;
        if (t < 56) { i = t;      W = W_fc1; a = b_fc1[i]; }
        else        { i = t - 56; W = W_fc2; a = b_fc2[i]; }
        const float* wrow = W + i * (HID + 8);
        for (int k = 0; k < HID + 8; ++k) a = fmaf(hg[k], wrow[k], a);
        out[b * 112 + t] = a;
    }
}

// ---------------- launcher --------------------------------------------------
extern "C" void kernel_launch(void* const* d_in, const int* in_sizes, int n_in,
                              void* d_out, int out_size)
{
    const int*   types = (const int*)d_in[0];
    const int*   paths = (const int*)d_in[1];
    const int*   adj   = (const int*)d_in[2];
    const float* feats = (const float*)d_in[3];
    const float* W_ih  = (const float*)d_in[4];
    const float* W_hh  = (const float*)d_in[5];
    const float* b_ih  = (const float*)d_in[6];
    const float* b_hh  = (const float*)d_in[7];
    const float* Wg    = (const float*)d_in[8];
    const float* bg    = (const float*)d_in[9];
    const float* Wm    = (const float*)d_in[10];
    const float* W_df1 = (const float*)d_in[11];
    const float* b_df1 = (const float*)d_in[12];
    const float* W_df2 = (const float*)d_in[13];
    const float* b_df2 = (const float*)d_in[14];
    const float* W_fc1 = (const float*)d_in[15];
    const float* b_fc1 = (const float*)d_in[16];
    const float* W_fc2 = (const float*)d_in[17];
    const float* b_fc2 = (const float*)d_in[18];
    float* out = (float*)d_out;

    cudaFuncSetAttribute(k_ggru,  cudaFuncAttributeMaxDynamicSharedMemorySize, GRU_SMEM);
    cudaFuncSetAttribute(k_ggate, cudaFuncAttributeMaxDynamicSharedMemorySize, GT_SMEM);

    dim3 gGemm(BB / 128, KP / JT);   // 32 x 10

    k_pad<<<(5 * HID * HID + 255) / 256, 256>>>(W_hh, Wg, Wm);
    k_h0<<<(BB * HID + 255) / 256, 256>>>(types, paths, W_ih, b_ih, b_hh);

    k_ggate<<<gGemm, 256, GT_SMEM>>>(0, paths, Wg, bg, Wm);
    for (int v = 1; v < MAXN; ++v) {
        k_hin<<<BB / 4, 4 * KP4>>>(adj, v);
        k_ggru<<<gGemm, 256, GRU_SMEM>>>(v, types, paths, W_ih, b_ih, b_hh);
        if (v < MAXN - 1)
            k_ggate<<<gGemm, 256, GT_SMEM>>>(v, paths, Wg, bg, Wm);
    }
    k_head<<<BB, 128>>>(paths, feats, W_df1, b_df1, W_df2, b_df2,
                        W_fc1, b_fc1, W_fc2, b_fc2, out);
}